// round 7
// baseline (speedup 1.0000x reference)
#include <cuda_runtime.h>
#include <cstdint>

#define BB 8
#define MM 8192
#define DD 1024
#define GG 512

// Scratch (module globals; no runtime allocation)
__device__ float g_qg[(size_t)BB * MM * GG];   // 134 MB: tf32-rounded relu(qz @ W^T)
__device__ float g_Wr[(size_t)BB * GG * DD];   // 16.8 MB: tf32-rounded W [b,g,d]
__device__ float g_Wt[(size_t)BB * DD * GG];   // 16.8 MB: tf32-rounded W^T [b,d,g]
__device__ float g_psum[(size_t)BB * 64 * 4 * 128];  // per-CTA partial row L1 sums

__device__ __forceinline__ float to_tf32(float x) {
    float y; asm("cvt.rna.tf32.f32 %0,%1;" : "=f"(y) : "f"(x)); return y;
}
__device__ __forceinline__ void ldsm4(uint32_t r[4], uint32_t addr) {
    asm volatile("ldmatrix.sync.aligned.m8n8.x4.shared.b16 {%0,%1,%2,%3}, [%4];"
        : "=r"(r[0]), "=r"(r[1]), "=r"(r[2]), "=r"(r[3]) : "r"(addr));
}
__device__ __forceinline__ void mma8(float c[4], const uint32_t a[4],
                                     uint32_t b0, uint32_t b1) {
    asm volatile(
        "mma.sync.aligned.m16n8k8.row.col.f32.tf32.tf32.f32 "
        "{%0,%1,%2,%3},{%4,%5,%6,%7},{%8,%9},{%0,%1,%2,%3};"
        : "+f"(c[0]), "+f"(c[1]), "+f"(c[2]), "+f"(c[3])
        : "r"(a[0]), "r"(a[1]), "r"(a[2]), "r"(a[3]), "r"(b0), "r"(b1));
}
__device__ __forceinline__ uint32_t smem_u32(const void* p) {
    uint32_t a;
    asm("{ .reg .u64 t; cvta.to.shared.u64 t, %1; cvt.u32.u64 %0, t; }" : "=r"(a) : "l"(p));
    return a;
}
#define CPA(dst, src) \
    asm volatile("cp.async.cg.shared.global [%0], [%1], 16;" :: "r"(dst), "l"(src) : "memory")
#define CPA_COMMIT() asm volatile("cp.async.commit_group;" ::: "memory")
#define CPA_WAIT(n)  asm volatile("cp.async.wait_group %0;" :: "n"(n) : "memory")

// ---------------------------------------------------------------------------
// Prep: round+transpose W in one pass -> g_Wr and g_Wt
// ---------------------------------------------------------------------------
__global__ __launch_bounds__(256) void prep_W(const float* __restrict__ W) {
    __shared__ float t[32][33];
    int b = blockIdx.z;
    int d0 = blockIdx.x * 32, g0 = blockIdx.y * 32;
    int x = threadIdx.x & 31, y = threadIdx.x >> 5;
    const float* src = W + (size_t)b * GG * DD;
    float* dstT = g_Wt + (size_t)b * DD * GG;
    float* dstR = g_Wr + (size_t)b * GG * DD;
#pragma unroll
    for (int i = 0; i < 32; i += 8) {
        float v = to_tf32(src[(size_t)(g0 + y + i) * DD + d0 + x]);
        t[y + i][x] = v;
        dstR[(size_t)(g0 + y + i) * DD + d0 + x] = v;
    }
    __syncthreads();
#pragma unroll
    for (int i = 0; i < 32; i += 8)
        dstT[(size_t)(d0 + y + i) * GG + g0 + x] = t[x][y + i];
}

// ---------------------------------------------------------------------------
// NT GEMM: C[128x128] = A[128 x KTOT] * B[128 x KTOT]^T, K-major.
// 4 warps, warp tile 64x64, 3-stage ring, one barrier/iter, XOR swizzle,
// ldmatrix with HOISTED addresses.
// EPI 0: A = qz staged via regs (LDG+cvt+STS), B = g_Wr cp.async;
//        epilogue: relu + tf32 round -> g_qg, per-CTA row partials -> g_psum.
// EPI 1: A = g_qg, B = g_Wt, both cp.async; rows scaled by 1/L1 -> out.
// ---------------------------------------------------------------------------
template<int KTOT, int EPI>
__global__ __launch_bounds__(128) void gemm_v6(
    const float* __restrict__ Ain, float* __restrict__ Cout)
{
    constexpr int BK = 32;
    constexpr int NK = KTOT / BK;
    constexpr int LDC = (EPI == 0) ? GG : DD;
    // smem: A stages @ s*16384 (3), B stages @ 49152 + s*16384 (3), sinv @ 98304
    extern __shared__ __align__(128) char smem[];
    const uint32_t sb = smem_u32(smem);

    const int t    = threadIdx.x;
    const int lane = t & 31, w = t >> 5;
    const int gid  = lane >> 2, tig = lane & 3;
    const int warp_m = (w & 1) * 64;
    const int warp_n = (w >> 1) * 64;
    const int bx = blockIdx.x, by = blockIdx.y, b = blockIdx.z;
    const int bm = bx * 128, bn = by * 128;

    const float* Ag = ((EPI == 0) ? Ain : g_qg) + ((size_t)b * MM + bm) * KTOT;
    const float* Bg = ((EPI == 0) ? g_Wr : g_Wt) + ((size_t)b * LDC + bn) * KTOT;
    float* Cg = ((EPI == 0) ? g_qg : Cout) + ((size_t)b * MM + bm) * LDC + bn;

    // EPI1: build per-row inverse L1 norms from the 4 partials
    float* sinv = (float*)(smem + 98304);
    if (EPI == 1 && t < 128) {
        const float* ps = &g_psum[((size_t)(b * 64 + bx) * 4) * 128];
        float s = ps[t] + ps[128 + t] + ps[256 + t] + ps[384 + t];
        sinv[t] = 1.f / fmaxf(s, 1e-6f);
    }

    float acc[4][8][4];
#pragma unroll
    for (int i = 0; i < 4; i++)
#pragma unroll
        for (int j = 0; j < 8; j++)
#pragma unroll
            for (int k = 0; k < 4; k++) acc[i][j][k] = 0.f;

    // ---- cp.async of one 128x32 tile (16KB): 8 x 16B per thread ----
    const int ld_row = t >> 3, ld_g = t & 7;
    const uint32_t ld_soff =
        (uint32_t)(ld_row * 128) + (uint32_t)((ld_g ^ (ld_row & 7)) << 4);
    auto ISSUE_B = [&](int it) {
        const int k0 = it * BK;
        const uint32_t base = sb + 49152 + (it % 3) * 16384;
#pragma unroll
        for (int j = 0; j < 8; j++)   // rows ld_row + 16j
            CPA(base + ld_soff + j * 2048,
                Bg + (size_t)(ld_row + 16 * j) * KTOT + k0 + ld_g * 4);
    };
    auto ISSUE_A = [&](int it) {   // EPI==1 only
        const int k0 = it * BK;
        const uint32_t base = sb + (it % 3) * 16384;
#pragma unroll
        for (int j = 0; j < 8; j++)
            CPA(base + ld_soff + j * 2048,
                Ag + (size_t)(ld_row + 16 * j) * KTOT + k0 + ld_g * 4);
    };

    // ---- staged A path for EPI==0 (needs cvt.rna) ----
    float4 ar[8];
    auto LOAD_A = [&](int it) {
        const int k0 = it * BK;
#pragma unroll
        for (int j = 0; j < 8; j++)
            ar[j] = *(const float4*)(Ag + (size_t)(ld_row + 16 * j) * KTOT + k0 + ld_g * 4);
    };
    auto STORE_A = [&](int it) {
        char* base = smem + (it % 3) * 16384;
#pragma unroll
        for (int j = 0; j < 8; j++) {
            float4 v = ar[j];
            v.x = to_tf32(v.x); v.y = to_tf32(v.y);
            v.z = to_tf32(v.z); v.w = to_tf32(v.w);
            *(float4*)(base + ld_soff + j * 2048) = v;
        }
    };

    // ---- hoisted ldmatrix addresses ----
    const int mat   = lane >> 3;
    const int rsub  = (mat & 1) * 8 + (lane & 7);
    const uint32_t gh4 = (uint32_t)(mat >> 1) << 4;   // ghalf<<4
    uint32_t aoff[4], boff[4];
#pragma unroll
    for (int i = 0; i < 4; i++) {
        int ra = warp_m + i * 16 + rsub;
        int rb = warp_n + i * 16 + rsub;
        aoff[i] = (uint32_t)(ra * 128) + (uint32_t)((ra & 7) << 4);
        boff[i] = (uint32_t)(rb * 128) + (uint32_t)((rb & 7) << 4);
    }

    uint32_t fA[2][4][4], fB[2][4][4];
    auto LDFRAG = [&](uint32_t abase, uint32_t bbase, int ks, int pb) {
        const uint32_t gx = ((uint32_t)ks << 5) | gh4;  // grp<<4
#pragma unroll
        for (int mf = 0; mf < 4; mf++)
            ldsm4(fA[pb][mf], (abase + aoff[mf]) ^ gx);
#pragma unroll
        for (int nb = 0; nb < 4; nb++)
            ldsm4(fB[pb][nb], (bbase + boff[nb]) ^ gx);
    };
    auto MMAS = [&](int pb) {
#pragma unroll
        for (int nb = 0; nb < 4; nb++)
#pragma unroll
            for (int mf = 0; mf < 4; mf++) {
                mma8(acc[mf][2 * nb],     fA[pb][mf], fB[pb][nb][0], fB[pb][nb][2]);
                mma8(acc[mf][2 * nb + 1], fA[pb][mf], fB[pb][nb][1], fB[pb][nb][3]);
            }
    };

    // ---- prologue: 2 stages in flight ----
    if (EPI == 0) {
        ISSUE_B(0); CPA_COMMIT();
        ISSUE_B(1); CPA_COMMIT();
        LOAD_A(0); STORE_A(0); LOAD_A(1);
    } else {
        ISSUE_A(0); ISSUE_B(0); CPA_COMMIT();
        ISSUE_A(1); ISSUE_B(1); CPA_COMMIT();
    }

#pragma unroll 1
    for (int it = 0; it < NK; ++it) {
        if (it + 1 < NK) CPA_WAIT(1); else CPA_WAIT(0);
        __syncthreads();                 // stage `it` visible; COMP(it-1) done by all
        if (it + 2 < NK) {
            if (EPI == 0) ISSUE_B(it + 2);
            else          { ISSUE_A(it + 2); ISSUE_B(it + 2); }
            CPA_COMMIT();
        }
        if (EPI == 0) {
            if (it + 1 < NK) STORE_A(it + 1);
            if (it + 2 < NK) LOAD_A(it + 2);
        }
        const uint32_t abase = sb + (it % 3) * 16384;
        const uint32_t bbase = abase + 49152;
        if (EPI == 0) {                  // single frag buffer (reg pressure)
#pragma unroll
            for (int ks = 0; ks < 4; ks++) { LDFRAG(abase, bbase, ks, 0); MMAS(0); }
        } else {                         // double-buffered frags
            LDFRAG(abase, bbase, 0, 0);
#pragma unroll
            for (int ks = 0; ks < 4; ks++) {
                if (ks < 3) LDFRAG(abase, bbase, ks + 1, (ks + 1) & 1);
                MMAS(ks & 1);
            }
        }
    }

    // ---- epilogue ----
    float s0[4], s1[4];
#pragma unroll
    for (int mf = 0; mf < 4; mf++) { s0[mf] = 0.f; s1[mf] = 0.f; }

#pragma unroll
    for (int mf = 0; mf < 4; mf++) {
        int r0 = warp_m + mf * 16 + gid;
        float i0 = 1.f, i1 = 1.f;
        if (EPI == 1) { i0 = sinv[r0]; i1 = sinv[r0 + 8]; }
#pragma unroll
        for (int nf = 0; nf < 8; nf++) {
            int c0 = warp_n + nf * 8 + tig * 2;
            float2 v0, v1;
            if (EPI == 0) {
                v0 = make_float2(to_tf32(fmaxf(acc[mf][nf][0], 0.f)),
                                 to_tf32(fmaxf(acc[mf][nf][1], 0.f)));
                v1 = make_float2(to_tf32(fmaxf(acc[mf][nf][2], 0.f)),
                                 to_tf32(fmaxf(acc[mf][nf][3], 0.f)));
                s0[mf] += v0.x + v0.y;
                s1[mf] += v1.x + v1.y;
            } else {
                v0 = make_float2(acc[mf][nf][0] * i0, acc[mf][nf][1] * i0);
                v1 = make_float2(acc[mf][nf][2] * i1, acc[mf][nf][3] * i1);
            }
            *(float2*)(Cg + (size_t)r0 * LDC + c0)       = v0;
            *(float2*)(Cg + (size_t)(r0 + 8) * LDC + c0) = v1;
        }
    }

    if (EPI == 0) {
#pragma unroll
        for (int mf = 0; mf < 4; mf++) {
            s0[mf] += __shfl_xor_sync(0xffffffffu, s0[mf], 1);
            s0[mf] += __shfl_xor_sync(0xffffffffu, s0[mf], 2);
            s1[mf] += __shfl_xor_sync(0xffffffffu, s1[mf], 1);
            s1[mf] += __shfl_xor_sync(0xffffffffu, s1[mf], 2);
        }
        __syncthreads();                 // stages no longer needed; reuse smem
        float* ps = (float*)smem;        // [2][128]: per n-half row sums
        if (tig == 0) {
#pragma unroll
            for (int mf = 0; mf < 4; mf++) {
                int r0 = warp_m + mf * 16 + gid;
                ps[(w >> 1) * 128 + r0]     = s0[mf];
                ps[(w >> 1) * 128 + r0 + 8] = s1[mf];
            }
        }
        __syncthreads();
        if (t < 128)
            g_psum[((size_t)(b * 64 + bx) * 4 + by) * 128 + t] = ps[t] + ps[128 + t];
    }
}

// ---------------------------------------------------------------------------
extern "C" void kernel_launch(void* const* d_in, const int* in_sizes, int n_in,
                              void* d_out, int out_size)
{
    const float* qz = (const float*)d_in[0];
    const float* W  = (const float*)d_in[1];
    float* out = (float*)d_out;

    constexpr int SMEM = 98816;  // 3x16KB A + 3x16KB B + 512B sinv
    cudaFuncSetAttribute(gemm_v6<1024, 0>, cudaFuncAttributeMaxDynamicSharedMemorySize, SMEM);
    cudaFuncSetAttribute(gemm_v6<512, 1>,  cudaFuncAttributeMaxDynamicSharedMemorySize, SMEM);

    prep_W<<<dim3(DD / 32, GG / 32, BB), 256>>>(W);

    // qg = tf32(relu(qz @ W^T)) + per-CTA row partials  [K = 1024]
    gemm_v6<1024, 0><<<dim3(MM / 128, GG / 128, BB), 128, SMEM>>>(qz, nullptr);

    // msg = (qg / L1) @ W  via Wt  [K = 512], norm built from partials
    gemm_v6<512, 1><<<dim3(MM / 128, DD / 128, BB), 128, SMEM>>>(nullptr, out);
}

// round 9
// speedup vs baseline: 1.0308x; 1.0308x over previous
#include <cuda_runtime.h>
#include <cstdint>

#define BB 8
#define MM 8192
#define DD 1024
#define GG 512

// Scratch (module globals; no runtime allocation)
__device__ float g_qg[(size_t)BB * MM * GG];   // 134 MB: tf32-rounded relu(qz @ W^T)
__device__ float g_Wr[(size_t)BB * GG * DD];   // 16.8 MB: tf32-rounded W [b,g,d]
__device__ float g_Wt[(size_t)BB * DD * GG];   // 16.8 MB: tf32-rounded W^T [b,d,g]
__device__ float g_psum[(size_t)BB * 64 * 4 * 128];  // per-CTA partial row L1 sums

__device__ __forceinline__ float to_tf32(float x) {
    float y; asm("cvt.rna.tf32.f32 %0,%1;" : "=f"(y) : "f"(x)); return y;
}
__device__ __forceinline__ void ldsm4(uint32_t r[4], uint32_t addr) {
    asm volatile("ldmatrix.sync.aligned.m8n8.x4.shared.b16 {%0,%1,%2,%3}, [%4];"
        : "=r"(r[0]), "=r"(r[1]), "=r"(r[2]), "=r"(r[3]) : "r"(addr));
}
__device__ __forceinline__ void mma8(float c[4], const uint32_t a[4],
                                     uint32_t b0, uint32_t b1) {
    asm volatile(
        "mma.sync.aligned.m16n8k8.row.col.f32.tf32.tf32.f32 "
        "{%0,%1,%2,%3},{%4,%5,%6,%7},{%8,%9},{%0,%1,%2,%3};"
        : "+f"(c[0]), "+f"(c[1]), "+f"(c[2]), "+f"(c[3])
        : "r"(a[0]), "r"(a[1]), "r"(a[2]), "r"(a[3]), "r"(b0), "r"(b1));
}
__device__ __forceinline__ uint32_t smem_u32(const void* p) {
    uint32_t a;
    asm("{ .reg .u64 t; cvta.to.shared.u64 t, %1; cvt.u32.u64 %0, t; }" : "=r"(a) : "l"(p));
    return a;
}
#define CPA(dst, src) \
    asm volatile("cp.async.cg.shared.global [%0], [%1], 16;" :: "r"(dst), "l"(src) : "memory")
#define CPA_COMMIT() asm volatile("cp.async.commit_group;" ::: "memory")
#define CPA_WAIT(n)  asm volatile("cp.async.wait_group %0;" :: "n"(n) : "memory")

// ---------------------------------------------------------------------------
// Prep: round+transpose W in one pass -> g_Wr and g_Wt
// ---------------------------------------------------------------------------
__global__ __launch_bounds__(256) void prep_W(const float* __restrict__ W) {
    __shared__ float t[32][33];
    int b = blockIdx.z;
    int d0 = blockIdx.x * 32, g0 = blockIdx.y * 32;
    int x = threadIdx.x & 31, y = threadIdx.x >> 5;
    const float* src = W + (size_t)b * GG * DD;
    float* dstT = g_Wt + (size_t)b * DD * GG;
    float* dstR = g_Wr + (size_t)b * GG * DD;
#pragma unroll
    for (int i = 0; i < 32; i += 8) {
        float v = to_tf32(src[(size_t)(g0 + y + i) * DD + d0 + x]);
        t[y + i][x] = v;
        dstR[(size_t)(g0 + y + i) * DD + d0 + x] = v;
    }
    __syncthreads();
#pragma unroll
    for (int i = 0; i < 32; i += 8)
        dstT[(size_t)(d0 + y + i) * GG + g0 + x] = t[x][y + i];
}

// ===========================================================================
// GEMM 1 (v4-measured structure): qg = tf32(relu(qz @ W^T)), K = 1024.
// 2-stage double buffer, TWO barriers/iter, staged-A (LDG+cvt+STS),
// B via cp.async. 4 warps, warp tile 64x64. Epilogue adds psum partials.
// smem: A0@0 A1@16K B0@32K B1@48K  (64KB)
// ===========================================================================
__global__ __launch_bounds__(128) void gemm1(const float* __restrict__ Ain)
{
    constexpr int KTOT = DD, BK = 32, NK = KTOT / BK, LDC = GG;
    extern __shared__ __align__(128) char smem[];
    const uint32_t sb = smem_u32(smem);

    const int t    = threadIdx.x;
    const int lane = t & 31, w = t >> 5;
    const int gid  = lane >> 2, tig = lane & 3;
    const int warp_m = (w & 1) * 64;
    const int warp_n = (w >> 1) * 64;
    const int bx = blockIdx.x, by = blockIdx.y, b = blockIdx.z;
    const int bm = bx * 128, bn = by * 128;

    const float* Ag = Ain + ((size_t)b * MM + bm) * KTOT;
    const float* Bg = g_Wr + ((size_t)b * LDC + bn) * KTOT;
    float* Cg = g_qg + ((size_t)b * MM + bm) * LDC + bn;

    float acc[4][8][4];
#pragma unroll
    for (int i = 0; i < 4; i++)
#pragma unroll
        for (int j = 0; j < 8; j++)
#pragma unroll
            for (int k = 0; k < 4; k++) acc[i][j][k] = 0.f;

    auto ISSUE_B = [&](int it) {
        const int k0 = it * BK;
        const uint32_t base = sb + 32768 + (it & 1) * 16384;
#pragma unroll
        for (int j = 0; j < 8; j++) {
            int i = t + j * 128, row = i >> 3, g = i & 7;
            uint32_t off = (uint32_t)(row * 128) + (uint32_t)((g ^ (row & 7)) << 4);
            CPA(base + off, Bg + (size_t)row * KTOT + k0 + g * 4);
        }
    };

    float4 ar[8];
    auto LOAD_A = [&](int it) {
        const int k0 = it * BK;
#pragma unroll
        for (int j = 0; j < 8; j++) {
            int i = t + j * 128, row = i >> 3, g = i & 7;
            ar[j] = *(const float4*)(Ag + (size_t)row * KTOT + k0 + g * 4);
        }
    };
    auto STORE_A = [&](int it) {
        char* base = smem + (it & 1) * 16384;
#pragma unroll
        for (int j = 0; j < 8; j++) {
            int i = t + j * 128, row = i >> 3, g = i & 7;
            uint32_t off = (uint32_t)(row * 128) + (uint32_t)((g ^ (row & 7)) << 4);
            float4 v = ar[j];
            v.x = to_tf32(v.x); v.y = to_tf32(v.y);
            v.z = to_tf32(v.z); v.w = to_tf32(v.w);
            *(float4*)(base + off) = v;
        }
    };

    const int mat   = lane >> 3;
    const int rsub  = (mat & 1) * 8 + (lane & 7);
    const int ghalf = mat >> 1;

    auto COMP = [&](int buf) {
        const uint32_t abase = sb + buf * 16384;
        const uint32_t bbase = sb + 32768 + buf * 16384;
#pragma unroll
        for (int ks = 0; ks < 4; ks++) {
            const int grp = 2 * ks + ghalf;
            uint32_t afr[4][4];
#pragma unroll
            for (int mf = 0; mf < 4; mf++) {
                int rr = warp_m + mf * 16 + rsub;
                ldsm4(afr[mf], abase + rr * 128 + ((grp ^ (rr & 7)) << 4));
            }
#pragma unroll
            for (int nb = 0; nb < 4; nb++) {
                uint32_t bfr[4];
                int rr = warp_n + nb * 16 + rsub;
                ldsm4(bfr, bbase + rr * 128 + ((grp ^ (rr & 7)) << 4));
#pragma unroll
                for (int mf = 0; mf < 4; mf++) {
                    mma8(acc[mf][2 * nb],     afr[mf], bfr[0], bfr[2]);
                    mma8(acc[mf][2 * nb + 1], afr[mf], bfr[1], bfr[3]);
                }
            }
        }
    };

    // prologue
    ISSUE_B(0); CPA_COMMIT();
    ISSUE_B(1); CPA_COMMIT();
    LOAD_A(0); STORE_A(0); LOAD_A(1);

#pragma unroll 1
    for (int it = 0; it < NK; ++it) {
        if (it == NK - 1) CPA_WAIT(0); else CPA_WAIT(1);
        __syncthreads();
        COMP(it & 1);
        __syncthreads();
        if (it + 2 < NK) { ISSUE_B(it + 2); CPA_COMMIT(); }
        if (it + 1 < NK) STORE_A(it + 1);
        if (it + 2 < NK) LOAD_A(it + 2);
    }

    // epilogue: relu + tf32 round -> g_qg, accumulate row partials
    float s0[4], s1[4];
#pragma unroll
    for (int mf = 0; mf < 4; mf++) { s0[mf] = 0.f; s1[mf] = 0.f; }

#pragma unroll
    for (int mf = 0; mf < 4; mf++) {
        int r0 = warp_m + mf * 16 + gid;
#pragma unroll
        for (int nf = 0; nf < 8; nf++) {
            int c0 = warp_n + nf * 8 + tig * 2;
            float2 v0 = make_float2(to_tf32(fmaxf(acc[mf][nf][0], 0.f)),
                                    to_tf32(fmaxf(acc[mf][nf][1], 0.f)));
            float2 v1 = make_float2(to_tf32(fmaxf(acc[mf][nf][2], 0.f)),
                                    to_tf32(fmaxf(acc[mf][nf][3], 0.f)));
            s0[mf] += v0.x + v0.y;
            s1[mf] += v1.x + v1.y;
            *(float2*)(Cg + (size_t)r0 * LDC + c0)       = v0;
            *(float2*)(Cg + (size_t)(r0 + 8) * LDC + c0) = v1;
        }
    }
#pragma unroll
    for (int mf = 0; mf < 4; mf++) {
        s0[mf] += __shfl_xor_sync(0xffffffffu, s0[mf], 1);
        s0[mf] += __shfl_xor_sync(0xffffffffu, s0[mf], 2);
        s1[mf] += __shfl_xor_sync(0xffffffffu, s1[mf], 1);
        s1[mf] += __shfl_xor_sync(0xffffffffu, s1[mf], 2);
    }
    __syncthreads();                 // stage buffers no longer needed; reuse
    float* ps = (float*)smem;        // [2][128]
    if (tig == 0) {
#pragma unroll
        for (int mf = 0; mf < 4; mf++) {
            int r0 = warp_m + mf * 16 + gid;
            ps[(w >> 1) * 128 + r0]     = s0[mf];
            ps[(w >> 1) * 128 + r0 + 8] = s1[mf];
        }
    }
    __syncthreads();
    if (t < 128)
        g_psum[((size_t)(b * 64 + bx) * 4 + by) * 128 + t] = ps[t] + ps[128 + t];
}

// ===========================================================================
// GEMM 2 (v5-measured structure): msg = (qg / L1) @ W via Wt, K = 512.
// 3-stage ring, ONE barrier/iter, all cp.async, double-buffered frags.
// smem: A s*16K (3), B 49152+s*16K (3), sinv @98304
// ===========================================================================
__global__ __launch_bounds__(128) void gemm2(float* __restrict__ Cout)
{
    constexpr int KTOT = GG, BK = 32, NK = KTOT / BK, LDC = DD;
    extern __shared__ __align__(128) char smem[];
    const uint32_t sb = smem_u32(smem);

    const int t    = threadIdx.x;
    const int lane = t & 31, w = t >> 5;
    const int gid  = lane >> 2, tig = lane & 3;
    const int warp_m = (w & 1) * 64;
    const int warp_n = (w >> 1) * 64;
    const int bx = blockIdx.x, by = blockIdx.y, b = blockIdx.z;
    const int bm = bx * 128, bn = by * 128;

    const float* Ag = g_qg + ((size_t)b * MM + bm) * KTOT;
    const float* Bg = g_Wt + ((size_t)b * LDC + bn) * KTOT;
    float* Cg = Cout + ((size_t)b * MM + bm) * LDC + bn;

    float* sinv = (float*)(smem + 98304);
    if (t < 128) {
        const float* ps = &g_psum[((size_t)(b * 64 + bx) * 4) * 128];
        float s = ps[t] + ps[128 + t] + ps[256 + t] + ps[384 + t];
        sinv[t] = 1.f / fmaxf(s, 1e-6f);
    }

    float acc[4][8][4];
#pragma unroll
    for (int i = 0; i < 4; i++)
#pragma unroll
        for (int j = 0; j < 8; j++)
#pragma unroll
            for (int k = 0; k < 4; k++) acc[i][j][k] = 0.f;

    auto ISSUE = [&](int it) {
        const int k0 = it * BK;
        const int s = it % 3;
        const uint32_t abase = sb + s * 16384;
        const uint32_t bbase = sb + 49152 + s * 16384;
#pragma unroll
        for (int j = 0; j < 8; j++) {
            int i = t + j * 128, row = i >> 3, g = i & 7;
            uint32_t off = (uint32_t)(row * 128) + (uint32_t)((g ^ (row & 7)) << 4);
            CPA(abase + off, Ag + (size_t)row * KTOT + k0 + g * 4);
            CPA(bbase + off, Bg + (size_t)row * KTOT + k0 + g * 4);
        }
    };

    const int mat   = lane >> 3;
    const int rsub  = (mat & 1) * 8 + (lane & 7);
    const int ghalf = mat >> 1;

    uint32_t fA[2][4][4], fB[2][4][4];
    auto LDFRAG = [&](int s, int ks, int pb) {
        const uint32_t abase = sb + s * 16384;
        const uint32_t bbase = sb + 49152 + s * 16384;
        const int grp = 2 * ks + ghalf;
#pragma unroll
        for (int mf = 0; mf < 4; mf++) {
            int rr = warp_m + mf * 16 + rsub;
            ldsm4(fA[pb][mf], abase + rr * 128 + ((grp ^ (rr & 7)) << 4));
        }
#pragma unroll
        for (int nb = 0; nb < 4; nb++) {
            int rr = warp_n + nb * 16 + rsub;
            ldsm4(fB[pb][nb], bbase + rr * 128 + ((grp ^ (rr & 7)) << 4));
        }
    };
    auto MMAS = [&](int pb) {
#pragma unroll
        for (int nb = 0; nb < 4; nb++)
#pragma unroll
            for (int mf = 0; mf < 4; mf++) {
                mma8(acc[mf][2 * nb],     fA[pb][mf], fB[pb][nb][0], fB[pb][nb][2]);
                mma8(acc[mf][2 * nb + 1], fA[pb][mf], fB[pb][nb][1], fB[pb][nb][3]);
            }
    };

    ISSUE(0); CPA_COMMIT();
    ISSUE(1); CPA_COMMIT();

#pragma unroll 1
    for (int it = 0; it < NK; ++it) {
        if (it + 1 < NK) CPA_WAIT(1); else CPA_WAIT(0);
        __syncthreads();
        if (it + 2 < NK) { ISSUE(it + 2); CPA_COMMIT(); }
        const int s = it % 3;
        LDFRAG(s, 0, 0);
#pragma unroll
        for (int ks = 0; ks < 4; ks++) {
            if (ks < 3) LDFRAG(s, ks + 1, (ks + 1) & 1);
            MMAS(ks & 1);
        }
    }

    // epilogue: scale rows by 1/L1
#pragma unroll
    for (int mf = 0; mf < 4; mf++) {
        int r0 = warp_m + mf * 16 + gid;
        float i0 = sinv[r0], i1 = sinv[r0 + 8];
#pragma unroll
        for (int nf = 0; nf < 8; nf++) {
            int c0 = warp_n + nf * 8 + tig * 2;
            float2 v0 = make_float2(acc[mf][nf][0] * i0, acc[mf][nf][1] * i0);
            float2 v1 = make_float2(acc[mf][nf][2] * i1, acc[mf][nf][3] * i1);
            *(float2*)(Cg + (size_t)r0 * LDC + c0)       = v0;
            *(float2*)(Cg + (size_t)(r0 + 8) * LDC + c0) = v1;
        }
    }
}

// ---------------------------------------------------------------------------
extern "C" void kernel_launch(void* const* d_in, const int* in_sizes, int n_in,
                              void* d_out, int out_size)
{
    const float* qz = (const float*)d_in[0];
    const float* W  = (const float*)d_in[1];
    float* out = (float*)d_out;

    constexpr int SMEM1 = 65536;   // 2x16KB A + 2x16KB B
    constexpr int SMEM2 = 98816;   // 3x16KB A + 3x16KB B + 512B sinv
    cudaFuncSetAttribute(gemm1, cudaFuncAttributeMaxDynamicSharedMemorySize, SMEM1);
    cudaFuncSetAttribute(gemm2, cudaFuncAttributeMaxDynamicSharedMemorySize, SMEM2);

    prep_W<<<dim3(DD / 32, GG / 32, BB), 256>>>(W);

    gemm1<<<dim3(MM / 128, GG / 128, BB), 128, SMEM1>>>(qz);
    gemm2<<<dim3(MM / 128, DD / 128, BB), 128, SMEM2>>>(out);
}

// round 10
// speedup vs baseline: 1.0514x; 1.0200x over previous
#include <cuda_runtime.h>
#include <cstdint>

#define BB 8
#define MM 8192
#define DD 1024
#define GG 512

// Scratch (module globals; no runtime allocation)
__device__ float g_qg[(size_t)BB * MM * GG];   // 134 MB: tf32-rounded relu(qz @ W^T)
__device__ float g_Wr[(size_t)BB * GG * DD];   // 16.8 MB: tf32-rounded W [b,g,d]
__device__ float g_Wt[(size_t)BB * DD * GG];   // 16.8 MB: tf32-rounded W^T [b,d,g]
__device__ float g_psum[(size_t)BB * 64 * 4 * 128];  // per-CTA partial row L1 sums

__device__ __forceinline__ float to_tf32(float x) {
    float y; asm("cvt.rna.tf32.f32 %0,%1;" : "=f"(y) : "f"(x)); return y;
}
__device__ __forceinline__ void ldsm4(uint32_t r[4], uint32_t addr) {
    asm volatile("ldmatrix.sync.aligned.m8n8.x4.shared.b16 {%0,%1,%2,%3}, [%4];"
        : "=r"(r[0]), "=r"(r[1]), "=r"(r[2]), "=r"(r[3]) : "r"(addr));
}
__device__ __forceinline__ void mma8(float c[4], const uint32_t a[4],
                                     uint32_t b0, uint32_t b1) {
    asm volatile(
        "mma.sync.aligned.m16n8k8.row.col.f32.tf32.tf32.f32 "
        "{%0,%1,%2,%3},{%4,%5,%6,%7},{%8,%9},{%0,%1,%2,%3};"
        : "+f"(c[0]), "+f"(c[1]), "+f"(c[2]), "+f"(c[3])
        : "r"(a[0]), "r"(a[1]), "r"(a[2]), "r"(a[3]), "r"(b0), "r"(b1));
}
__device__ __forceinline__ uint32_t smem_u32(const void* p) {
    uint32_t a;
    asm("{ .reg .u64 t; cvta.to.shared.u64 t, %1; cvt.u32.u64 %0, t; }" : "=r"(a) : "l"(p));
    return a;
}
#define CPA(dst, src) \
    asm volatile("cp.async.cg.shared.global [%0], [%1], 16;" :: "r"(dst), "l"(src) : "memory")
#define CPA_COMMIT() asm volatile("cp.async.commit_group;" ::: "memory")
#define CPA_WAIT(n)  asm volatile("cp.async.wait_group %0;" :: "n"(n) : "memory")

// ---------------------------------------------------------------------------
// Prep: round+transpose W in one pass -> g_Wr and g_Wt
// ---------------------------------------------------------------------------
__global__ __launch_bounds__(256) void prep_W(const float* __restrict__ W) {
    __shared__ float t[32][33];
    int b = blockIdx.z;
    int d0 = blockIdx.x * 32, g0 = blockIdx.y * 32;
    int x = threadIdx.x & 31, y = threadIdx.x >> 5;
    const float* src = W + (size_t)b * GG * DD;
    float* dstT = g_Wt + (size_t)b * DD * GG;
    float* dstR = g_Wr + (size_t)b * GG * DD;
#pragma unroll
    for (int i = 0; i < 32; i += 8) {
        float v = to_tf32(src[(size_t)(g0 + y + i) * DD + d0 + x]);
        t[y + i][x] = v;
        dstR[(size_t)(g0 + y + i) * DD + d0 + x] = v;
    }
    __syncthreads();
#pragma unroll
    for (int i = 0; i < 32; i += 8)
        dstT[(size_t)(d0 + y + i) * GG + g0 + x] = t[x][y + i];
}

// ===========================================================================
// GEMM 1 (unchanged, measured): qg = tf32(relu(qz @ W^T)), K = 1024.
// 2-stage double buffer, TWO barriers/iter, staged-A (LDG+cvt+STS),
// B via cp.async. 4 warps, warp tile 64x64. Epilogue adds psum partials.
// smem: A0@0 A1@16K B0@32K B1@48K  (64KB)
// ===========================================================================
__global__ __launch_bounds__(128) void gemm1(const float* __restrict__ Ain)
{
    constexpr int KTOT = DD, BK = 32, NK = KTOT / BK, LDC = GG;
    extern __shared__ __align__(128) char smem[];
    const uint32_t sb = smem_u32(smem);

    const int t    = threadIdx.x;
    const int lane = t & 31, w = t >> 5;
    const int gid  = lane >> 2, tig = lane & 3;
    const int warp_m = (w & 1) * 64;
    const int warp_n = (w >> 1) * 64;
    const int bx = blockIdx.x, by = blockIdx.y, b = blockIdx.z;
    const int bm = bx * 128, bn = by * 128;

    const float* Ag = Ain + ((size_t)b * MM + bm) * KTOT;
    const float* Bg = g_Wr + ((size_t)b * LDC + bn) * KTOT;
    float* Cg = g_qg + ((size_t)b * MM + bm) * LDC + bn;

    float acc[4][8][4];
#pragma unroll
    for (int i = 0; i < 4; i++)
#pragma unroll
        for (int j = 0; j < 8; j++)
#pragma unroll
            for (int k = 0; k < 4; k++) acc[i][j][k] = 0.f;

    auto ISSUE_B = [&](int it) {
        const int k0 = it * BK;
        const uint32_t base = sb + 32768 + (it & 1) * 16384;
#pragma unroll
        for (int j = 0; j < 8; j++) {
            int i = t + j * 128, row = i >> 3, g = i & 7;
            uint32_t off = (uint32_t)(row * 128) + (uint32_t)((g ^ (row & 7)) << 4);
            CPA(base + off, Bg + (size_t)row * KTOT + k0 + g * 4);
        }
    };

    float4 ar[8];
    auto LOAD_A = [&](int it) {
        const int k0 = it * BK;
#pragma unroll
        for (int j = 0; j < 8; j++) {
            int i = t + j * 128, row = i >> 3, g = i & 7;
            ar[j] = *(const float4*)(Ag + (size_t)row * KTOT + k0 + g * 4);
        }
    };
    auto STORE_A = [&](int it) {
        char* base = smem + (it & 1) * 16384;
#pragma unroll
        for (int j = 0; j < 8; j++) {
            int i = t + j * 128, row = i >> 3, g = i & 7;
            uint32_t off = (uint32_t)(row * 128) + (uint32_t)((g ^ (row & 7)) << 4);
            float4 v = ar[j];
            v.x = to_tf32(v.x); v.y = to_tf32(v.y);
            v.z = to_tf32(v.z); v.w = to_tf32(v.w);
            *(float4*)(base + off) = v;
        }
    };

    const int mat   = lane >> 3;
    const int rsub  = (mat & 1) * 8 + (lane & 7);
    const int ghalf = mat >> 1;

    auto COMP = [&](int buf) {
        const uint32_t abase = sb + buf * 16384;
        const uint32_t bbase = sb + 32768 + buf * 16384;
#pragma unroll
        for (int ks = 0; ks < 4; ks++) {
            const int grp = 2 * ks + ghalf;
            uint32_t afr[4][4];
#pragma unroll
            for (int mf = 0; mf < 4; mf++) {
                int rr = warp_m + mf * 16 + rsub;
                ldsm4(afr[mf], abase + rr * 128 + ((grp ^ (rr & 7)) << 4));
            }
#pragma unroll
            for (int nb = 0; nb < 4; nb++) {
                uint32_t bfr[4];
                int rr = warp_n + nb * 16 + rsub;
                ldsm4(bfr, bbase + rr * 128 + ((grp ^ (rr & 7)) << 4));
#pragma unroll
                for (int mf = 0; mf < 4; mf++) {
                    mma8(acc[mf][2 * nb],     afr[mf], bfr[0], bfr[2]);
                    mma8(acc[mf][2 * nb + 1], afr[mf], bfr[1], bfr[3]);
                }
            }
        }
    };

    // prologue
    ISSUE_B(0); CPA_COMMIT();
    ISSUE_B(1); CPA_COMMIT();
    LOAD_A(0); STORE_A(0); LOAD_A(1);

#pragma unroll 1
    for (int it = 0; it < NK; ++it) {
        if (it == NK - 1) CPA_WAIT(0); else CPA_WAIT(1);
        __syncthreads();
        COMP(it & 1);
        __syncthreads();
        if (it + 2 < NK) { ISSUE_B(it + 2); CPA_COMMIT(); }
        if (it + 1 < NK) STORE_A(it + 1);
        if (it + 2 < NK) LOAD_A(it + 2);
    }

    // epilogue: relu + tf32 round -> g_qg, accumulate row partials
    float s0[4], s1[4];
#pragma unroll
    for (int mf = 0; mf < 4; mf++) { s0[mf] = 0.f; s1[mf] = 0.f; }

#pragma unroll
    for (int mf = 0; mf < 4; mf++) {
        int r0 = warp_m + mf * 16 + gid;
#pragma unroll
        for (int nf = 0; nf < 8; nf++) {
            int c0 = warp_n + nf * 8 + tig * 2;
            float2 v0 = make_float2(to_tf32(fmaxf(acc[mf][nf][0], 0.f)),
                                    to_tf32(fmaxf(acc[mf][nf][1], 0.f)));
            float2 v1 = make_float2(to_tf32(fmaxf(acc[mf][nf][2], 0.f)),
                                    to_tf32(fmaxf(acc[mf][nf][3], 0.f)));
            s0[mf] += v0.x + v0.y;
            s1[mf] += v1.x + v1.y;
            *(float2*)(Cg + (size_t)r0 * LDC + c0)       = v0;
            *(float2*)(Cg + (size_t)(r0 + 8) * LDC + c0) = v1;
        }
    }
#pragma unroll
    for (int mf = 0; mf < 4; mf++) {
        s0[mf] += __shfl_xor_sync(0xffffffffu, s0[mf], 1);
        s0[mf] += __shfl_xor_sync(0xffffffffu, s0[mf], 2);
        s1[mf] += __shfl_xor_sync(0xffffffffu, s1[mf], 1);
        s1[mf] += __shfl_xor_sync(0xffffffffu, s1[mf], 2);
    }
    __syncthreads();                 // stage buffers no longer needed; reuse
    float* ps = (float*)smem;        // [2][128]
    if (tig == 0) {
#pragma unroll
        for (int mf = 0; mf < 4; mf++) {
            int r0 = warp_m + mf * 16 + gid;
            ps[(w >> 1) * 128 + r0]     = s0[mf];
            ps[(w >> 1) * 128 + r0 + 8] = s1[mf];
        }
    }
    __syncthreads();
    if (t < 128)
        g_psum[((size_t)(b * 64 + bx) * 4 + by) * 128 + t] = ps[t] + ps[128 + t];
}

// ===========================================================================
// GEMM 2 (NEW: 3 CTAs/SM): msg = (qg / L1) @ W via Wt, K = 512.
// 2-stage double buffer (64.5KB/CTA -> 3 CTAs fit), TWO barriers/iter,
// all cp.async, SINGLE-buffered frags, __launch_bounds__(128, 3) caps regs
// at 170 so 3 CTAs x 128 thr fit the regfile -> 12 warps/SM (3/SMSP).
// smem: A0@0 A1@16K B0@32K B1@48K sinv@64K
// ===========================================================================
__global__ __launch_bounds__(128, 3) void gemm2(float* __restrict__ Cout)
{
    constexpr int KTOT = GG, BK = 32, NK = KTOT / BK, LDC = DD;
    extern __shared__ __align__(128) char smem[];
    const uint32_t sb = smem_u32(smem);

    const int t    = threadIdx.x;
    const int lane = t & 31, w = t >> 5;
    const int gid  = lane >> 2, tig = lane & 3;
    const int warp_m = (w & 1) * 64;
    const int warp_n = (w >> 1) * 64;
    const int bx = blockIdx.x, by = blockIdx.y, b = blockIdx.z;
    const int bm = bx * 128, bn = by * 128;

    const float* Ag = g_qg + ((size_t)b * MM + bm) * KTOT;
    const float* Bg = g_Wt + ((size_t)b * LDC + bn) * KTOT;
    float* Cg = Cout + ((size_t)b * MM + bm) * LDC + bn;

    float* sinv = (float*)(smem + 65536);
    if (t < 128) {
        const float* ps = &g_psum[((size_t)(b * 64 + bx) * 4) * 128];
        float s = ps[t] + ps[128 + t] + ps[256 + t] + ps[384 + t];
        sinv[t] = 1.f / fmaxf(s, 1e-6f);
    }

    float acc[4][8][4];
#pragma unroll
    for (int i = 0; i < 4; i++)
#pragma unroll
        for (int j = 0; j < 8; j++)
#pragma unroll
            for (int k = 0; k < 4; k++) acc[i][j][k] = 0.f;

    auto ISSUE = [&](int it) {
        const int k0 = it * BK;
        const uint32_t abase = sb + (it & 1) * 16384;
        const uint32_t bbase = sb + 32768 + (it & 1) * 16384;
#pragma unroll
        for (int j = 0; j < 8; j++) {
            int i = t + j * 128, row = i >> 3, g = i & 7;
            uint32_t off = (uint32_t)(row * 128) + (uint32_t)((g ^ (row & 7)) << 4);
            CPA(abase + off, Ag + (size_t)row * KTOT + k0 + g * 4);
            CPA(bbase + off, Bg + (size_t)row * KTOT + k0 + g * 4);
        }
    };

    const int mat   = lane >> 3;
    const int rsub  = (mat & 1) * 8 + (lane & 7);
    const int ghalf = mat >> 1;

    auto COMP = [&](int buf) {
        const uint32_t abase = sb + buf * 16384;
        const uint32_t bbase = sb + 32768 + buf * 16384;
#pragma unroll
        for (int ks = 0; ks < 4; ks++) {
            const int grp = 2 * ks + ghalf;
            uint32_t afr[4][4];
#pragma unroll
            for (int mf = 0; mf < 4; mf++) {
                int rr = warp_m + mf * 16 + rsub;
                ldsm4(afr[mf], abase + rr * 128 + ((grp ^ (rr & 7)) << 4));
            }
#pragma unroll
            for (int nb = 0; nb < 4; nb++) {
                uint32_t bfr[4];
                int rr = warp_n + nb * 16 + rsub;
                ldsm4(bfr, bbase + rr * 128 + ((grp ^ (rr & 7)) << 4));
#pragma unroll
                for (int mf = 0; mf < 4; mf++) {
                    mma8(acc[mf][2 * nb],     afr[mf], bfr[0], bfr[2]);
                    mma8(acc[mf][2 * nb + 1], afr[mf], bfr[1], bfr[3]);
                }
            }
        }
    };

    // prologue: 2 stages in flight
    ISSUE(0); CPA_COMMIT();
    ISSUE(1); CPA_COMMIT();

#pragma unroll 1
    for (int it = 0; it < NK; ++it) {
        if (it == NK - 1) CPA_WAIT(0); else CPA_WAIT(1);
        __syncthreads();
        COMP(it & 1);
        __syncthreads();
        if (it + 2 < NK) { ISSUE(it + 2); CPA_COMMIT(); }
    }

    // epilogue: scale rows by 1/L1
#pragma unroll
    for (int mf = 0; mf < 4; mf++) {
        int r0 = warp_m + mf * 16 + gid;
        float i0 = sinv[r0], i1 = sinv[r0 + 8];
#pragma unroll
        for (int nf = 0; nf < 8; nf++) {
            int c0 = warp_n + nf * 8 + tig * 2;
            float2 v0 = make_float2(acc[mf][nf][0] * i0, acc[mf][nf][1] * i0);
            float2 v1 = make_float2(acc[mf][nf][2] * i1, acc[mf][nf][3] * i1);
            *(float2*)(Cg + (size_t)r0 * LDC + c0)       = v0;
            *(float2*)(Cg + (size_t)(r0 + 8) * LDC + c0) = v1;
        }
    }
}

// ---------------------------------------------------------------------------
extern "C" void kernel_launch(void* const* d_in, const int* in_sizes, int n_in,
                              void* d_out, int out_size)
{
    const float* qz = (const float*)d_in[0];
    const float* W  = (const float*)d_in[1];
    float* out = (float*)d_out;

    constexpr int SMEM1 = 65536;   // 2x16KB A + 2x16KB B
    constexpr int SMEM2 = 66048;   // 2x16KB A + 2x16KB B + 512B sinv
    cudaFuncSetAttribute(gemm1, cudaFuncAttributeMaxDynamicSharedMemorySize, SMEM1);
    cudaFuncSetAttribute(gemm2, cudaFuncAttributeMaxDynamicSharedMemorySize, SMEM2);

    prep_W<<<dim3(DD / 32, GG / 32, BB), 256>>>(W);

    gemm1<<<dim3(MM / 128, GG / 128, BB), 128, SMEM1>>>(qz);
    gemm2<<<dim3(MM / 128, DD / 128, BB), 128, SMEM2>>>(out);
}

// round 12
// speedup vs baseline: 1.0870x; 1.0338x over previous
#include <cuda_runtime.h>
#include <cstdint>

#define BB 8
#define MM 8192
#define DD 1024
#define GG 512

// Scratch (module globals; no runtime allocation)
__device__ float g_qg[(size_t)BB * MM * GG];   // 134 MB: tf32-rounded relu(qz @ W^T)
__device__ float g_Wr[(size_t)BB * GG * DD];   // 16.8 MB: tf32-rounded W [b,g,d]
__device__ float g_Wt[(size_t)BB * DD * GG];   // 16.8 MB: tf32-rounded W^T [b,d,g]
__device__ float g_psum[(size_t)BB * 64 * 4 * 128];  // per-CTA partial row L1 sums
__device__ unsigned int g_ctr[2];              // dynamic tile counters

__device__ __forceinline__ float to_tf32(float x) {
    float y; asm("cvt.rna.tf32.f32 %0,%1;" : "=f"(y) : "f"(x)); return y;
}
__device__ __forceinline__ void ldsm4(uint32_t r[4], uint32_t addr) {
    asm volatile("ldmatrix.sync.aligned.m8n8.x4.shared.b16 {%0,%1,%2,%3}, [%4];"
        : "=r"(r[0]), "=r"(r[1]), "=r"(r[2]), "=r"(r[3]) : "r"(addr));
}
__device__ __forceinline__ void mma8(float c[4], const uint32_t a[4],
                                     uint32_t b0, uint32_t b1) {
    asm volatile(
        "mma.sync.aligned.m16n8k8.row.col.f32.tf32.tf32.f32 "
        "{%0,%1,%2,%3},{%4,%5,%6,%7},{%8,%9},{%0,%1,%2,%3};"
        : "+f"(c[0]), "+f"(c[1]), "+f"(c[2]), "+f"(c[3])
        : "r"(a[0]), "r"(a[1]), "r"(a[2]), "r"(a[3]), "r"(b0), "r"(b1));
}
__device__ __forceinline__ uint32_t smem_u32(const void* p) {
    uint32_t a;
    asm("{ .reg .u64 t; cvta.to.shared.u64 t, %1; cvt.u32.u64 %0, t; }" : "=r"(a) : "l"(p));
    return a;
}
#define CPA(dst, src) \
    asm volatile("cp.async.cg.shared.global [%0], [%1], 16;" :: "r"(dst), "l"(src) : "memory")
#define CPA_COMMIT() asm volatile("cp.async.commit_group;" ::: "memory")
#define CPA_WAIT(n)  asm volatile("cp.async.wait_group %0;" :: "n"(n) : "memory")

__global__ void reset_ctr() { g_ctr[0] = 0; g_ctr[1] = 0; }

// ---------------------------------------------------------------------------
// Prep: round+transpose W in one pass -> g_Wr and g_Wt
// ---------------------------------------------------------------------------
__global__ __launch_bounds__(256) void prep_W(const float* __restrict__ W) {
    __shared__ float t[32][33];
    int b = blockIdx.z;
    int d0 = blockIdx.x * 32, g0 = blockIdx.y * 32;
    int x = threadIdx.x & 31, y = threadIdx.x >> 5;
    const float* src = W + (size_t)b * GG * DD;
    float* dstT = g_Wt + (size_t)b * DD * GG;
    float* dstR = g_Wr + (size_t)b * GG * DD;
#pragma unroll
    for (int i = 0; i < 32; i += 8) {
        float v = to_tf32(src[(size_t)(g0 + y + i) * DD + d0 + x]);
        t[y + i][x] = v;
        dstR[(size_t)(g0 + y + i) * DD + d0 + x] = v;
    }
    __syncthreads();
#pragma unroll
    for (int i = 0; i < 32; i += 8)
        dstT[(size_t)(d0 + y + i) * GG + g0 + x] = t[x][y + i];
}

// ===========================================================================
// GEMM 1: qg = tf32(relu(qz @ W^T)), K = 1024. PERSISTENT + 3 CTAs/SM.
// Both operands via cp.async; A is RAW qz, rounded per-fragment after
// ldmatrix (bit-identical to pre-rounding). 2-stage, two barriers/iter.
// smem: A0@0 A1@16K B0@32K B1@48K tilep@64K
// ===========================================================================
__global__ __launch_bounds__(128, 3) void gemm1(const float* __restrict__ Ain)
{
    constexpr int KTOT = DD, BK = 32, NK = KTOT / BK, LDC = GG, NT = 2048;
    extern __shared__ __align__(128) char smem[];
    const uint32_t sb = smem_u32(smem);
    int* tilep = (int*)(smem + 65536);

    const int t    = threadIdx.x;
    const int lane = t & 31, w = t >> 5;
    const int gid  = lane >> 2, tig = lane & 3;
    const int warp_m = (w & 1) * 64;
    const int warp_n = (w >> 1) * 64;
    const int mat   = lane >> 3;
    const int rsub  = (mat & 1) * 8 + (lane & 7);
    const int ghalf = mat >> 1;

    while (true) {
        __syncthreads();                       // protect smem reuse across tiles
        if (t == 0) *tilep = (int)atomicAdd(&g_ctr[0], 1u);
        __syncthreads();
        const int tile = *tilep;
        if (tile >= NT) break;
        const int bx = tile & 63, by = (tile >> 6) & 3, b = tile >> 8;
        const int bm = bx * 128, bn = by * 128;

        const float* Ag = Ain + ((size_t)b * MM + bm) * KTOT;
        const float* Bg = g_Wr + ((size_t)b * LDC + bn) * KTOT;
        float* Cg = g_qg + ((size_t)b * MM + bm) * LDC + bn;

        float acc[4][8][4];
#pragma unroll
        for (int i = 0; i < 4; i++)
#pragma unroll
            for (int j = 0; j < 8; j++)
#pragma unroll
                for (int k = 0; k < 4; k++) acc[i][j][k] = 0.f;

        auto ISSUE = [&](int it) {
            const int k0 = it * BK;
            const uint32_t abase = sb + (it & 1) * 16384;
            const uint32_t bbase = sb + 32768 + (it & 1) * 16384;
#pragma unroll
            for (int j = 0; j < 8; j++) {
                int i = t + j * 128, row = i >> 3, g = i & 7;
                uint32_t off = (uint32_t)(row * 128) + (uint32_t)((g ^ (row & 7)) << 4);
                CPA(abase + off, Ag + (size_t)row * KTOT + k0 + g * 4);
                CPA(bbase + off, Bg + (size_t)row * KTOT + k0 + g * 4);
            }
        };
        auto COMP = [&](int buf) {
            const uint32_t abase = sb + buf * 16384;
            const uint32_t bbase = sb + 32768 + buf * 16384;
#pragma unroll
            for (int ks = 0; ks < 4; ks++) {
                const int grp = 2 * ks + ghalf;
                uint32_t afr[4][4];
#pragma unroll
                for (int mf = 0; mf < 4; mf++) {
                    int rr = warp_m + mf * 16 + rsub;
                    ldsm4(afr[mf], abase + rr * 128 + ((grp ^ (rr & 7)) << 4));
                }
                // round A fragments to tf32 (bit-identical to pre-rounding)
#pragma unroll
                for (int mf = 0; mf < 4; mf++)
#pragma unroll
                    for (int r = 0; r < 4; r++)
                        afr[mf][r] = __float_as_uint(to_tf32(__uint_as_float(afr[mf][r])));
#pragma unroll
                for (int nb = 0; nb < 4; nb++) {
                    uint32_t bfr[4];
                    int rr = warp_n + nb * 16 + rsub;
                    ldsm4(bfr, bbase + rr * 128 + ((grp ^ (rr & 7)) << 4));
#pragma unroll
                    for (int mf = 0; mf < 4; mf++) {
                        mma8(acc[mf][2 * nb],     afr[mf], bfr[0], bfr[2]);
                        mma8(acc[mf][2 * nb + 1], afr[mf], bfr[1], bfr[3]);
                    }
                }
            }
        };

        ISSUE(0); CPA_COMMIT();
        ISSUE(1); CPA_COMMIT();
#pragma unroll 1
        for (int it = 0; it < NK; ++it) {
            if (it == NK - 1) CPA_WAIT(0); else CPA_WAIT(1);
            __syncthreads();
            COMP(it & 1);
            __syncthreads();
            if (it + 2 < NK) { ISSUE(it + 2); CPA_COMMIT(); }
        }

        // epilogue: relu + tf32 round -> g_qg, accumulate row partials
        float s0[4], s1[4];
#pragma unroll
        for (int mf = 0; mf < 4; mf++) { s0[mf] = 0.f; s1[mf] = 0.f; }
#pragma unroll
        for (int mf = 0; mf < 4; mf++) {
            int r0 = warp_m + mf * 16 + gid;
#pragma unroll
            for (int nf = 0; nf < 8; nf++) {
                int c0 = warp_n + nf * 8 + tig * 2;
                float2 v0 = make_float2(to_tf32(fmaxf(acc[mf][nf][0], 0.f)),
                                        to_tf32(fmaxf(acc[mf][nf][1], 0.f)));
                float2 v1 = make_float2(to_tf32(fmaxf(acc[mf][nf][2], 0.f)),
                                        to_tf32(fmaxf(acc[mf][nf][3], 0.f)));
                s0[mf] += v0.x + v0.y;
                s1[mf] += v1.x + v1.y;
                *(float2*)(Cg + (size_t)r0 * LDC + c0)       = v0;
                *(float2*)(Cg + (size_t)(r0 + 8) * LDC + c0) = v1;
            }
        }
#pragma unroll
        for (int mf = 0; mf < 4; mf++) {
            s0[mf] += __shfl_xor_sync(0xffffffffu, s0[mf], 1);
            s0[mf] += __shfl_xor_sync(0xffffffffu, s0[mf], 2);
            s1[mf] += __shfl_xor_sync(0xffffffffu, s1[mf], 1);
            s1[mf] += __shfl_xor_sync(0xffffffffu, s1[mf], 2);
        }
        __syncthreads();               // stage buffers free; reuse for ps
        float* ps = (float*)smem;      // [2][128]
        if (tig == 0) {
#pragma unroll
            for (int mf = 0; mf < 4; mf++) {
                int r0 = warp_m + mf * 16 + gid;
                ps[(w >> 1) * 128 + r0]     = s0[mf];
                ps[(w >> 1) * 128 + r0 + 8] = s1[mf];
            }
        }
        __syncthreads();
        if (t < 128)
            g_psum[((size_t)(b * 64 + bx) * 4 + by) * 128 + t] = ps[t] + ps[128 + t];
    }
}

// ===========================================================================
// GEMM 2: msg = (qg / L1) @ W via Wt, K = 512. PERSISTENT + 3 CTAs/SM.
// 2-stage, two barriers/iter, all cp.async, single-buffered frags.
// smem: A0@0 A1@16K B0@32K B1@48K sinv@64K tilep@64K+512
// ===========================================================================
__global__ __launch_bounds__(128, 3) void gemm2(float* __restrict__ Cout)
{
    constexpr int KTOT = GG, BK = 32, NK = KTOT / BK, LDC = DD, NT = 4096;
    extern __shared__ __align__(128) char smem[];
    const uint32_t sb = smem_u32(smem);
    float* sinv = (float*)(smem + 65536);
    int* tilep = (int*)(smem + 66048);

    const int t    = threadIdx.x;
    const int lane = t & 31, w = t >> 5;
    const int gid  = lane >> 2, tig = lane & 3;
    const int warp_m = (w & 1) * 64;
    const int warp_n = (w >> 1) * 64;
    const int mat   = lane >> 3;
    const int rsub  = (mat & 1) * 8 + (lane & 7);
    const int ghalf = mat >> 1;

    while (true) {
        __syncthreads();                       // protect smem reuse across tiles
        if (t == 0) *tilep = (int)atomicAdd(&g_ctr[1], 1u);
        __syncthreads();
        const int tile = *tilep;
        if (tile >= NT) break;
        const int bx = tile & 63, by = (tile >> 6) & 7, b = tile >> 9;
        const int bm = bx * 128, bn = by * 128;

        const float* Ag = g_qg + ((size_t)b * MM + bm) * KTOT;
        const float* Bg = g_Wt + ((size_t)b * LDC + bn) * KTOT;
        float* Cg = Cout + ((size_t)b * MM + bm) * LDC + bn;

        if (t < 128) {
            const float* ps = &g_psum[((size_t)(b * 64 + bx) * 4) * 128];
            float s = ps[t] + ps[128 + t] + ps[256 + t] + ps[384 + t];
            sinv[t] = 1.f / fmaxf(s, 1e-6f);
        }

        float acc[4][8][4];
#pragma unroll
        for (int i = 0; i < 4; i++)
#pragma unroll
            for (int j = 0; j < 8; j++)
#pragma unroll
                for (int k = 0; k < 4; k++) acc[i][j][k] = 0.f;

        auto ISSUE = [&](int it) {
            const int k0 = it * BK;
            const uint32_t abase = sb + (it & 1) * 16384;
            const uint32_t bbase = sb + 32768 + (it & 1) * 16384;
#pragma unroll
            for (int j = 0; j < 8; j++) {
                int i = t + j * 128, row = i >> 3, g = i & 7;
                uint32_t off = (uint32_t)(row * 128) + (uint32_t)((g ^ (row & 7)) << 4);
                CPA(abase + off, Ag + (size_t)row * KTOT + k0 + g * 4);
                CPA(bbase + off, Bg + (size_t)row * KTOT + k0 + g * 4);
            }
        };
        auto COMP = [&](int buf) {
            const uint32_t abase = sb + buf * 16384;
            const uint32_t bbase = sb + 32768 + buf * 16384;
#pragma unroll
            for (int ks = 0; ks < 4; ks++) {
                const int grp = 2 * ks + ghalf;
                uint32_t afr[4][4];
#pragma unroll
                for (int mf = 0; mf < 4; mf++) {
                    int rr = warp_m + mf * 16 + rsub;
                    ldsm4(afr[mf], abase + rr * 128 + ((grp ^ (rr & 7)) << 4));
                }
#pragma unroll
                for (int nb = 0; nb < 4; nb++) {
                    uint32_t bfr[4];
                    int rr = warp_n + nb * 16 + rsub;
                    ldsm4(bfr, bbase + rr * 128 + ((grp ^ (rr & 7)) << 4));
#pragma unroll
                    for (int mf = 0; mf < 4; mf++) {
                        mma8(acc[mf][2 * nb],     afr[mf], bfr[0], bfr[2]);
                        mma8(acc[mf][2 * nb + 1], afr[mf], bfr[1], bfr[3]);
                    }
                }
            }
        };

        ISSUE(0); CPA_COMMIT();
        ISSUE(1); CPA_COMMIT();
#pragma unroll 1
        for (int it = 0; it < NK; ++it) {
            if (it == NK - 1) CPA_WAIT(0); else CPA_WAIT(1);
            __syncthreads();
            COMP(it & 1);
            __syncthreads();
            if (it + 2 < NK) { ISSUE(it + 2); CPA_COMMIT(); }
        }

        // epilogue: scale rows by 1/L1
#pragma unroll
        for (int mf = 0; mf < 4; mf++) {
            int r0 = warp_m + mf * 16 + gid;
            float i0 = sinv[r0], i1 = sinv[r0 + 8];
#pragma unroll
            for (int nf = 0; nf < 8; nf++) {
                int c0 = warp_n + nf * 8 + tig * 2;
                float2 v0 = make_float2(acc[mf][nf][0] * i0, acc[mf][nf][1] * i0);
                float2 v1 = make_float2(acc[mf][nf][2] * i1, acc[mf][nf][3] * i1);
                *(float2*)(Cg + (size_t)r0 * LDC + c0)       = v0;
                *(float2*)(Cg + (size_t)(r0 + 8) * LDC + c0) = v1;
            }
        }
    }
}

// ---------------------------------------------------------------------------
extern "C" void kernel_launch(void* const* d_in, const int* in_sizes, int n_in,
                              void* d_out, int out_size)
{
    const float* qz = (const float*)d_in[0];
    const float* W  = (const float*)d_in[1];
    float* out = (float*)d_out;

    constexpr int SMEM1 = 65664;   // 4x16KB stages + tilep
    constexpr int SMEM2 = 66176;   // 4x16KB stages + sinv + tilep
    cudaFuncSetAttribute(gemm1, cudaFuncAttributeMaxDynamicSharedMemorySize, SMEM1);
    cudaFuncSetAttribute(gemm2, cudaFuncAttributeMaxDynamicSharedMemorySize, SMEM2);

    reset_ctr<<<1, 1>>>();
    prep_W<<<dim3(DD / 32, GG / 32, BB), 256>>>(W);

    constexpr int PERSIST = 148 * 3;
    gemm1<<<PERSIST, 128, SMEM1>>>(qz);
    gemm2<<<PERSIST, 128, SMEM2>>>(out);
}

// round 17
// speedup vs baseline: 1.0930x; 1.0056x over previous
#include <cuda_runtime.h>
#include <cstdint>

#define BB 8
#define MM 8192
#define DD 1024
#define GG 512

// Scratch (module globals; no runtime allocation)
__device__ float g_qg[(size_t)BB * MM * GG];   // 134 MB: tf32-rounded relu(qz @ W^T)
__device__ float g_Wr[(size_t)BB * GG * DD];   // 16.8 MB: tf32-rounded W [b,g,d]
__device__ float g_Wt[(size_t)BB * DD * GG];   // 16.8 MB: tf32-rounded W^T [b,d,g]
__device__ float g_psum[(size_t)BB * 64 * 4 * 128];  // per-rowblock partial L1 sums
__device__ unsigned int g_ctr;                 // fused work-queue counter
__device__ unsigned int g_flag[BB * 64];       // per-rowblock producer-done count

__device__ __forceinline__ float to_tf32(float x) {
    float y; asm("cvt.rna.tf32.f32 %0,%1;" : "=f"(y) : "f"(x)); return y;
}
__device__ __forceinline__ void ldsm4(uint32_t r[4], uint32_t addr) {
    asm volatile("ldmatrix.sync.aligned.m8n8.x4.shared.b16 {%0,%1,%2,%3}, [%4];"
        : "=r"(r[0]), "=r"(r[1]), "=r"(r[2]), "=r"(r[3]) : "r"(addr));
}
__device__ __forceinline__ void mma8(float c[4], const uint32_t a[4],
                                     uint32_t b0, uint32_t b1) {
    asm volatile(
        "mma.sync.aligned.m16n8k8.row.col.f32.tf32.tf32.f32 "
        "{%0,%1,%2,%3},{%4,%5,%6,%7},{%8,%9},{%0,%1,%2,%3};"
        : "+f"(c[0]), "+f"(c[1]), "+f"(c[2]), "+f"(c[3])
        : "r"(a[0]), "r"(a[1]), "r"(a[2]), "r"(a[3]), "r"(b0), "r"(b1));
}
__device__ __forceinline__ uint32_t smem_u32(const void* p) {
    uint32_t a;
    asm("{ .reg .u64 t; cvta.to.shared.u64 t, %1; cvt.u32.u64 %0, t; }" : "=r"(a) : "l"(p));
    return a;
}
#define CPA(dst, src) \
    asm volatile("cp.async.cg.shared.global [%0], [%1], 16;" :: "r"(dst), "l"(src) : "memory")
#define CPA_COMMIT() asm volatile("cp.async.commit_group;" ::: "memory")
#define CPA_WAIT(n)  asm volatile("cp.async.wait_group %0;" :: "n"(n) : "memory")

__global__ __launch_bounds__(512) void reset_state() {
    if (threadIdx.x == 0) g_ctr = 0;
    g_flag[threadIdx.x] = 0;
}

// ---------------------------------------------------------------------------
// Prep: round+transpose W in one pass -> g_Wr and g_Wt
// ---------------------------------------------------------------------------
__global__ __launch_bounds__(256) void prep_W(const float* __restrict__ W) {
    __shared__ float t[32][33];
    int b = blockIdx.z;
    int d0 = blockIdx.x * 32, g0 = blockIdx.y * 32;
    int x = threadIdx.x & 31, y = threadIdx.x >> 5;
    const float* src = W + (size_t)b * GG * DD;
    float* dstT = g_Wt + (size_t)b * DD * GG;
    float* dstR = g_Wr + (size_t)b * GG * DD;
#pragma unroll
    for (int i = 0; i < 32; i += 8) {
        float v = to_tf32(src[(size_t)(g0 + y + i) * DD + d0 + x]);
        t[y + i][x] = v;
        dstR[(size_t)(g0 + y + i) * DD + d0 + x] = v;
    }
    __syncthreads();
#pragma unroll
    for (int i = 0; i < 32; i += 8)
        dstT[(size_t)(d0 + y + i) * GG + g0 + x] = t[x][y + i];
}

// ===========================================================================
// FUSED persistent kernel: one queue of 6144 tiles.
//   idx in [0, 2048):   GEMM1 tile  (b, bx, by) = (idx>>8, (idx>>2)&63, idx&3)
//                       qg_tile = tf32(relu(qz @ W^T)), psum partial,
//                       then fence + flag[b*64+bx] += 1.
//   idx in [2048, 6144): GEMM2 tile j = idx-2048, (b,bx,by)=(j>>9,(j>>3)&63,j&7)
//                       spin until flag[rowblock]==4, sinv from psum,
//                       msg_tile = (qg/L1) @ Wt.
// 2-stage smem ring, two barriers/iter, warp tile 64x64, 3 CTAs/SM.
// smem: A0@0 A1@16K B0@32K B1@48K sinv@64K tilep@64K+512
// ===========================================================================
__global__ __launch_bounds__(128, 3) void fused_gemm(
    const float* __restrict__ qz, float* __restrict__ out)
{
    constexpr int NT1 = 2048, NT = 6144;
    extern __shared__ __align__(128) char smem[];
    const uint32_t sb = smem_u32(smem);
    float* sinv = (float*)(smem + 65536);
    int* tilep = (int*)(smem + 66048);

    const int t    = threadIdx.x;
    const int lane = t & 31, w = t >> 5;
    const int gid  = lane >> 2, tig = lane & 3;
    const int warp_m = (w & 1) * 64;
    const int warp_n = (w >> 1) * 64;
    const int mat   = lane >> 3;
    const int rsub  = (mat & 1) * 8 + (lane & 7);
    const int ghalf = mat >> 1;

    while (true) {
        __syncthreads();                         // protect smem reuse across tiles
        if (t == 0) *tilep = (int)atomicAdd(&g_ctr, 1u);
        __syncthreads();
        const int idx = *tilep;
        if (idx >= NT) break;

        if (idx < NT1) {
            // ---------------- GEMM 1 tile (K = 1024) ----------------
            constexpr int KTOT = DD, BK = 32, NK = KTOT / BK, LDC = GG;
            const int by = idx & 3, bx = (idx >> 2) & 63, b = idx >> 8;
            const int bm = bx * 128, bn = by * 128;

            const float* Ag = qz + ((size_t)b * MM + bm) * KTOT;
            const float* Bg = g_Wr + ((size_t)b * LDC + bn) * KTOT;
            float* Cg = g_qg + ((size_t)b * MM + bm) * LDC + bn;

            float acc[4][8][4];
#pragma unroll
            for (int i = 0; i < 4; i++)
#pragma unroll
                for (int j = 0; j < 8; j++)
#pragma unroll
                    for (int k = 0; k < 4; k++) acc[i][j][k] = 0.f;

            auto ISSUE = [&](int it) {
                const int k0 = it * BK;
                const uint32_t abase = sb + (it & 1) * 16384;
                const uint32_t bbase = sb + 32768 + (it & 1) * 16384;
#pragma unroll
                for (int j = 0; j < 8; j++) {
                    int i = t + j * 128, row = i >> 3, g = i & 7;
                    uint32_t off = (uint32_t)(row * 128) + (uint32_t)((g ^ (row & 7)) << 4);
                    CPA(abase + off, Ag + (size_t)row * KTOT + k0 + g * 4);
                    CPA(bbase + off, Bg + (size_t)row * KTOT + k0 + g * 4);
                }
            };
            auto COMP = [&](int buf) {
                const uint32_t abase = sb + buf * 16384;
                const uint32_t bbase = sb + 32768 + buf * 16384;
#pragma unroll
                for (int ks = 0; ks < 4; ks++) {
                    const int grp = 2 * ks + ghalf;
                    uint32_t afr[4][4];
#pragma unroll
                    for (int mf = 0; mf < 4; mf++) {
                        int rr = warp_m + mf * 16 + rsub;
                        ldsm4(afr[mf], abase + rr * 128 + ((grp ^ (rr & 7)) << 4));
                    }
#pragma unroll
                    for (int mf = 0; mf < 4; mf++)
#pragma unroll
                        for (int r = 0; r < 4; r++)
                            afr[mf][r] = __float_as_uint(to_tf32(__uint_as_float(afr[mf][r])));
#pragma unroll
                    for (int nb = 0; nb < 4; nb++) {
                        uint32_t bfr[4];
                        int rr = warp_n + nb * 16 + rsub;
                        ldsm4(bfr, bbase + rr * 128 + ((grp ^ (rr & 7)) << 4));
#pragma unroll
                        for (int mf = 0; mf < 4; mf++) {
                            mma8(acc[mf][2 * nb],     afr[mf], bfr[0], bfr[2]);
                            mma8(acc[mf][2 * nb + 1], afr[mf], bfr[1], bfr[3]);
                        }
                    }
                }
            };

            ISSUE(0); CPA_COMMIT();
            ISSUE(1); CPA_COMMIT();
#pragma unroll 1
            for (int it = 0; it < NK; ++it) {
                if (it == NK - 1) CPA_WAIT(0); else CPA_WAIT(1);
                __syncthreads();
                COMP(it & 1);
                __syncthreads();
                if (it + 2 < NK) { ISSUE(it + 2); CPA_COMMIT(); }
            }

            float s0[4], s1[4];
#pragma unroll
            for (int mf = 0; mf < 4; mf++) { s0[mf] = 0.f; s1[mf] = 0.f; }
#pragma unroll
            for (int mf = 0; mf < 4; mf++) {
                int r0 = warp_m + mf * 16 + gid;
#pragma unroll
                for (int nf = 0; nf < 8; nf++) {
                    int c0 = warp_n + nf * 8 + tig * 2;
                    float2 v0 = make_float2(to_tf32(fmaxf(acc[mf][nf][0], 0.f)),
                                            to_tf32(fmaxf(acc[mf][nf][1], 0.f)));
                    float2 v1 = make_float2(to_tf32(fmaxf(acc[mf][nf][2], 0.f)),
                                            to_tf32(fmaxf(acc[mf][nf][3], 0.f)));
                    s0[mf] += v0.x + v0.y;
                    s1[mf] += v1.x + v1.y;
                    *(float2*)(Cg + (size_t)r0 * LDC + c0)       = v0;
                    *(float2*)(Cg + (size_t)(r0 + 8) * LDC + c0) = v1;
                }
            }
#pragma unroll
            for (int mf = 0; mf < 4; mf++) {
                s0[mf] += __shfl_xor_sync(0xffffffffu, s0[mf], 1);
                s0[mf] += __shfl_xor_sync(0xffffffffu, s0[mf], 2);
                s1[mf] += __shfl_xor_sync(0xffffffffu, s1[mf], 1);
                s1[mf] += __shfl_xor_sync(0xffffffffu, s1[mf], 2);
            }
            __syncthreads();           // stage buffers free; reuse for ps
            float* ps = (float*)smem;  // [2][128]
            if (tig == 0) {
#pragma unroll
                for (int mf = 0; mf < 4; mf++) {
                    int r0 = warp_m + mf * 16 + gid;
                    ps[(w >> 1) * 128 + r0]     = s0[mf];
                    ps[(w >> 1) * 128 + r0 + 8] = s1[mf];
                }
            }
            __syncthreads();
            if (t < 128)
                g_psum[((size_t)(b * 64 + bx) * 4 + by) * 128 + t] = ps[t] + ps[128 + t];
            __syncthreads();           // all psum/qg stores issued
            if (t == 0) {
                __threadfence();       // publish qg tile + psum before flag
                atomicAdd(&g_flag[b * 64 + bx], 1u);
            }
        } else {
            // ---------------- GEMM 2 tile (K = 512) ----------------
            constexpr int KTOT = GG, BK = 32, NK = KTOT / BK, LDC = DD;
            const int j = idx - NT1;
            const int by = j & 7, bx = (j >> 3) & 63, b = j >> 9;
            const int bm = bx * 128, bn = by * 128;
            const int rb = b * 64 + bx;

            if (t == 0) {              // wait for all 4 producer tiles
                while (atomicAdd(&g_flag[rb], 0u) < 4u) __nanosleep(128);
                __threadfence();       // acquire: order subsequent reads
            }
            __syncthreads();

            const float* Ag = g_qg + ((size_t)b * MM + bm) * KTOT;
            const float* Bg = g_Wt + ((size_t)b * LDC + bn) * KTOT;
            float* Cg = out + ((size_t)b * MM + bm) * LDC + bn;

            if (t < 128) {
                const float* ps = &g_psum[((size_t)rb * 4) * 128];
                float s = ps[t] + ps[128 + t] + ps[256 + t] + ps[384 + t];
                sinv[t] = 1.f / fmaxf(s, 1e-6f);
            }

            float acc[4][8][4];
#pragma unroll
            for (int i = 0; i < 4; i++)
#pragma unroll
                for (int jj = 0; jj < 8; jj++)
#pragma unroll
                    for (int k = 0; k < 4; k++) acc[i][jj][k] = 0.f;

            auto ISSUE = [&](int it) {
                const int k0 = it * BK;
                const uint32_t abase = sb + (it & 1) * 16384;
                const uint32_t bbase = sb + 32768 + (it & 1) * 16384;
#pragma unroll
                for (int jj = 0; jj < 8; jj++) {
                    int i = t + jj * 128, row = i >> 3, g = i & 7;
                    uint32_t off = (uint32_t)(row * 128) + (uint32_t)((g ^ (row & 7)) << 4);
                    CPA(abase + off, Ag + (size_t)row * KTOT + k0 + g * 4);
                    CPA(bbase + off, Bg + (size_t)row * KTOT + k0 + g * 4);
                }
            };
            auto COMP = [&](int buf) {
                const uint32_t abase = sb + buf * 16384;
                const uint32_t bbase = sb + 32768 + buf * 16384;
#pragma unroll
                for (int ks = 0; ks < 4; ks++) {
                    const int grp = 2 * ks + ghalf;
                    uint32_t afr[4][4];
#pragma unroll
                    for (int mf = 0; mf < 4; mf++) {
                        int rr = warp_m + mf * 16 + rsub;
                        ldsm4(afr[mf], abase + rr * 128 + ((grp ^ (rr & 7)) << 4));
                    }
#pragma unroll
                    for (int nb = 0; nb < 4; nb++) {
                        uint32_t bfr[4];
                        int rr = warp_n + nb * 16 + rsub;
                        ldsm4(bfr, bbase + rr * 128 + ((grp ^ (rr & 7)) << 4));
#pragma unroll
                        for (int mf = 0; mf < 4; mf++) {
                            mma8(acc[mf][2 * nb],     afr[mf], bfr[0], bfr[2]);
                            mma8(acc[mf][2 * nb + 1], afr[mf], bfr[1], bfr[3]);
                        }
                    }
                }
            };

            ISSUE(0); CPA_COMMIT();
            ISSUE(1); CPA_COMMIT();
#pragma unroll 1
            for (int it = 0; it < NK; ++it) {
                if (it == NK - 1) CPA_WAIT(0); else CPA_WAIT(1);
                __syncthreads();
                COMP(it & 1);
                __syncthreads();
                if (it + 2 < NK) { ISSUE(it + 2); CPA_COMMIT(); }
            }

#pragma unroll
            for (int mf = 0; mf < 4; mf++) {
                int r0 = warp_m + mf * 16 + gid;
                float i0 = sinv[r0], i1 = sinv[r0 + 8];
#pragma unroll
                for (int nf = 0; nf < 8; nf++) {
                    int c0 = warp_n + nf * 8 + tig * 2;
                    float2 v0 = make_float2(acc[mf][nf][0] * i0, acc[mf][nf][1] * i0);
                    float2 v1 = make_float2(acc[mf][nf][2] * i1, acc[mf][nf][3] * i1);
                    *(float2*)(Cg + (size_t)r0 * LDC + c0)       = v0;
                    *(float2*)(Cg + (size_t)(r0 + 8) * LDC + c0) = v1;
                }
            }
        }
    }
}

// ---------------------------------------------------------------------------
extern "C" void kernel_launch(void* const* d_in, const int* in_sizes, int n_in,
                              void* d_out, int out_size)
{
    const float* qz = (const float*)d_in[0];
    const float* W  = (const float*)d_in[1];
    float* out = (float*)d_out;

    constexpr int SMEM = 66176;   // 4x16KB stages + sinv(512B) + tilep
    cudaFuncSetAttribute(fused_gemm, cudaFuncAttributeMaxDynamicSharedMemorySize, SMEM);

    reset_state<<<1, 512>>>();
    prep_W<<<dim3(DD / 32, GG / 32, BB), 256>>>(W);

    constexpr int PERSIST = 148 * 3;
    fused_gemm<<<PERSIST, 128, SMEM>>>(qz, out);
}